// round 3
// baseline (speedup 1.0000x reference)
#include <cuda_runtime.h>
#include <cstdint>

typedef unsigned long long ull;
#define MAXN 100096

__device__ float g_X [MAXN*128];
__device__ float g_AX[MAXN*128];
__device__ float g_HG[MAXN*128];
__device__ ull   g_keys [MAXN];
__device__ ull   g_candA[MAXN];
__device__ ull   g_candB[MAXN];
__device__ float g_xt [128*128];
__device__ float g_gi [128*384];
__device__ float g_gh [128*384];
__device__ float g_wev[128*128];
__device__ float g_deg [MAXN];
__device__ float g_dinv[MAXN];
__device__ float g_pinv;
__device__ int   g_e64;

__global__ void pnorm_kernel(const float* __restrict__ p){
    __shared__ float s[128];
    int i = threadIdx.x;
    float v = p[i];
    s[i] = v*v; __syncthreads();
    for (int o=64;o>0;o>>=1){ if (i<o) s[i]+=s[i+o]; __syncthreads(); }
    if (i==0) g_pinv = rsqrtf(s[0]);
}

__global__ void detect_kernel(const void* __restrict__ edge, int N){
    if (threadIdx.x==0){
        const long long* e = (const long long*)edge;
        int ok = 1;
        for (int i=0;i<8;i++){ long long v=e[i]; if (v<0 || v>=(long long)N) ok=0; }
        g_e64 = ok;
    }
}

__device__ __forceinline__ int edge_at(const void* edge, size_t idx){
    return g_e64 ? ((const int*)edge)[2*idx] : ((const int*)edge)[idx];
}

// C[N,128] = A[N,K] @ B[K,128]; mode 0: inputs@W1 +b +relu -> g_X; mode 1: g_AX@g_wev -> g_HG
__global__ __launch_bounds__(256) void gemm_kernel(const float* __restrict__ Aext,
                                                   const float* __restrict__ Bext,
                                                   const float* __restrict__ bias,
                                                   int N, int K, int mode){
    const float* A = (mode==0) ? Aext : g_AX;
    const float* B = (mode==0) ? Bext : g_wev;
    float*       C = (mode==0) ? g_X  : g_HG;
    __shared__ float sA[128*33];
    __shared__ float sW[32*132];
    int tid = threadIdx.x;
    int tx = tid & 15, ty = tid >> 4;
    int rowBase = blockIdx.x << 7;
    float acc[8][8];
#pragma unroll
    for (int i=0;i<8;i++)
#pragma unroll
        for (int j=0;j<8;j++) acc[i][j]=0.f;

    for (int kk=0; kk<K; kk+=32){
#pragma unroll
        for (int r=0;r<4;r++){
            int f = tid + (r<<8);
            int row = f>>3, kc4 = f&7;
            float4 v = make_float4(0.f,0.f,0.f,0.f);
            int gr = rowBase + row;
            if (gr < N) v = *(const float4*)(A + (size_t)gr*K + kk + (kc4<<2));
            int o = row*33 + (kc4<<2);
            sA[o]=v.x; sA[o+1]=v.y; sA[o+2]=v.z; sA[o+3]=v.w;
        }
#pragma unroll
        for (int r=0;r<4;r++){
            int f = tid + (r<<8);
            int kr = f>>5, c4 = f&31;
            *(float4*)&sW[kr*132 + (c4<<2)] = *(const float4*)(B + (size_t)(kk+kr)*128 + (c4<<2));
        }
        __syncthreads();
#pragma unroll 8
        for (int kc=0;kc<32;kc++){
            float a[8];
#pragma unroll
            for (int i=0;i<8;i++) a[i] = sA[(ty + (i<<4))*33 + kc];
            float4 w0 = *(const float4*)&sW[kc*132 + (tx<<3)];
            float4 w1 = *(const float4*)&sW[kc*132 + (tx<<3) + 4];
#pragma unroll
            for (int i=0;i<8;i++){
                acc[i][0]+=a[i]*w0.x; acc[i][1]+=a[i]*w0.y; acc[i][2]+=a[i]*w0.z; acc[i][3]+=a[i]*w0.w;
                acc[i][4]+=a[i]*w1.x; acc[i][5]+=a[i]*w1.y; acc[i][6]+=a[i]*w1.z; acc[i][7]+=a[i]*w1.w;
            }
        }
        __syncthreads();
    }
    float bj[8];
#pragma unroll
    for (int j=0;j<8;j++) bj[j] = bias ? bias[(tx<<3)+j] : 0.f;
#pragma unroll
    for (int i=0;i<8;i++){
        int gr = rowBase + ty + (i<<4);
        if (gr < N){
            float o[8];
#pragma unroll
            for (int j=0;j<8;j++){
                float t = acc[i][j] + bj[j];
                o[j] = (mode==0) ? fmaxf(t,0.f) : t;
            }
            float* cp = C + (size_t)gr*128 + (tx<<3);
            *(float4*)cp       = make_float4(o[0],o[1],o[2],o[3]);
            *(float4*)(cp + 4) = make_float4(o[4],o[5],o[6],o[7]);
        }
    }
}

__global__ void score_kernel(const float* __restrict__ p, int N){
    int t = blockIdx.x*blockDim.x + threadIdx.x;
    int w = t>>5, lane = t&31;
    if (w >= N) return;
    float4 a = ((const float4*)(g_X + ((size_t)w<<7)))[lane];
    float4 b = ((const float4*)p)[lane];
    float s = a.x*b.x + a.y*b.y + a.z*b.z + a.w*b.w;
#pragma unroll
    for (int o=16;o>0;o>>=1) s += __shfl_xor_sync(0xffffffffu, s, o);
    if (lane==0){
        float sc = tanhf(s * g_pinv);
        unsigned u = __float_as_uint(sc);
        unsigned ord = (u & 0x80000000u) ? ~u : (u | 0x80000000u);
        g_keys[w] = ((ull)ord << 32) | (ull)(0xFFFFFFFFu - (unsigned)w);
    }
}

__global__ void chunk_sort_kernel(int N){
    __shared__ ull s[128];
    int i = threadIdx.x;
    int g = (blockIdx.x<<7) + i;
    s[i] = (g < N) ? g_keys[g] : 0ULL;
    __syncthreads();
    for (int k=2;k<=128;k<<=1){
        for (int j=k>>1;j>0;j>>=1){
            int pi = i ^ j;
            ull x = s[i], y = s[pi];
            __syncthreads();
            bool desc = ((i & k) == 0);
            ull keep;
            if (i < pi) keep = desc ? (x>y?x:y) : (x<y?x:y);
            else        keep = desc ? (x<y?x:y) : (x>y?x:y);
            s[i] = keep;
            __syncthreads();
        }
    }
    g_candA[(blockIdx.x<<7)+i] = s[i];
}

__global__ void topk_merge(int M, int srcIsA){
    const ull* src = srcIsA ? g_candA : g_candB;
    ull*       dst = srcIsA ? g_candB : g_candA;
    __shared__ ull s[128];
    int b = blockIdx.x, i = threadIdx.x;
    int l0 = 2*b, l1 = 2*b+1;
    ull a = src[(l0<<7)+i];
    if (l1 >= M){ dst[(b<<7)+i] = a; return; }
    ull bb = src[(l1<<7) + (127 - i)];
    s[i] = (a > bb) ? a : bb;
    __syncthreads();
    for (int j=64;j>0;j>>=1){
        int pi = i ^ j;
        ull x = s[i], y = s[pi];
        __syncthreads();
        s[i] = (i < pi) ? (x>y?x:y) : (x<y?x:y);
        __syncthreads();
    }
    dst[(b<<7)+i] = s[i];
}

__global__ void build_xtilde(int finalIsA){
    const ull* top = finalIsA ? g_candA : g_candB;
    int k = blockIdx.x;
    ull key = top[k];
    unsigned idx = 0xFFFFFFFFu - (unsigned)(key & 0xFFFFFFFFull);
    unsigned ord = (unsigned)(key >> 32);
    unsigned u = (ord & 0x80000000u) ? (ord & 0x7FFFFFFFu) : ~ord;
    float val = __uint_as_float(u);
    g_xt[(k<<7) + threadIdx.x] = g_X[((size_t)idx<<7) + threadIdx.x] * val;
}

__global__ void gru_gemm(const float* __restrict__ W_ih, const float* __restrict__ W_hh,
                         const float* __restrict__ b_ih, const float* __restrict__ b_hh,
                         const float* __restrict__ h0){
    int j = blockIdx.x;      // gate row 0..383
    int isH = blockIdx.y;
    __shared__ float4 w[32];
    const float* W = isH ? W_hh : W_ih;
    if (threadIdx.x < 32) w[threadIdx.x] = ((const float4*)(W + (j<<7)))[threadIdx.x];
    __syncthreads();
    int k = threadIdx.x;     // batch row 0..127
    const float4* src = (const float4*)((isH ? h0 : g_xt) + (k<<7));
    float s = 0.f;
#pragma unroll
    for (int h=0;h<32;h++){
        float4 aa = src[h], ww = w[h];
        s += aa.x*ww.x + aa.y*ww.y + aa.z*ww.z + aa.w*ww.w;
    }
    s += isH ? b_hh[j] : b_ih[j];
    (isH ? g_gh : g_gi)[k*384 + j] = s;
}

__global__ void gates_kernel(const float* __restrict__ h0){
    int t = blockIdx.x*blockDim.x + threadIdx.x;
    int k = t >> 7, c = t & 127;
    float ir = g_gi[k*384 + c],       hr = g_gh[k*384 + c];
    float iz = g_gi[k*384 + 128 + c], hz = g_gh[k*384 + 128 + c];
    float in_= g_gi[k*384 + 256 + c], hn = g_gh[k*384 + 256 + c];
    float r = 1.f/(1.f + expf(-(ir+hr)));
    float z = 1.f/(1.f + expf(-(iz+hz)));
    float nn = tanhf(in_ + r*hn);
    g_wev[(k<<7)+c] = (1.f - z)*nn + z*h0[(k<<7)+c];
}

__global__ void deg_init(int N){
    int i = blockIdx.x*blockDim.x + threadIdx.x;
    if (i<N) g_deg[i] = 1.f;
}
__global__ void deg_count(const void* __restrict__ edge, int E){
    int e = blockIdx.x*blockDim.x + threadIdx.x;
    if (e >= E) return;
    atomicAdd(&g_deg[edge_at(edge, (size_t)E + e)], 1.f);
}
__global__ void dinv_kernel(int N){
    int i = blockIdx.x*blockDim.x + threadIdx.x;
    if (i<N) g_dinv[i] = rsqrtf(g_deg[i]);
}
__global__ void ax_init(int N){
    int i = blockIdx.x*blockDim.x + threadIdx.x;
    if (i < N*128){
        int nn = i >> 7;
        float d = g_dinv[nn];
        g_AX[i] = d*d*g_X[i];
    }
}
__global__ __launch_bounds__(256) void scatter_kernel(const void* __restrict__ edge, int E){
    int t = blockIdx.x*blockDim.x + threadIdx.x;
    int e = t >> 5;
    if (e >= E) return;
    int lane = t & 31;
    int r = edge_at(edge, (size_t)e);
    int c = edge_at(edge, (size_t)E + e);
    float nrm = g_dinv[r]*g_dinv[c];
    float4 v = ((const float4*)(g_X + ((size_t)r<<7)))[lane];
    v.x*=nrm; v.y*=nrm; v.z*=nrm; v.w*=nrm;
    atomicAdd(((float4*)(g_AX + ((size_t)c<<7))) + lane, v);
}

__global__ __launch_bounds__(256) void final_kernel(const float* __restrict__ W2,
                                                    const float* __restrict__ b2,
                                                    float* __restrict__ outq,
                                                    float* __restrict__ outh, int N){
    __shared__ float sW2[4096];
    for (int i=threadIdx.x;i<4096;i+=256) sW2[i]=W2[i];
    __syncthreads();
    int n = blockIdx.x*256 + threadIdx.x;
    if (n >= N) return;
    const float4* hg = (const float4*)(g_HG + ((size_t)n<<7));
    const float4* xx = (const float4*)(g_X  + ((size_t)n<<7));
    float4* ho = (float4*)(outh + (size_t)n*256);
    float q[16];
#pragma unroll
    for (int j=0;j<16;j++) q[j]=b2[j];
#pragma unroll 4
    for (int j4=0;j4<32;j4++){
        float4 v = hg[j4];
        ho[j4] = v;
        const float* w = &sW2[(j4<<2)*16];
        float vv[4] = {v.x,v.y,v.z,v.w};
#pragma unroll
        for (int c=0;c<4;c++)
#pragma unroll
            for (int j=0;j<16;j++) q[j] += vv[c]*w[c*16+j];
    }
#pragma unroll 4
    for (int j4=0;j4<32;j4++){
        float4 v = xx[j4];
        ho[32+j4] = v;
        const float* w = &sW2[2048 + (j4<<2)*16];
        float vv[4] = {v.x,v.y,v.z,v.w};
#pragma unroll
        for (int c=0;c<4;c++)
#pragma unroll
            for (int j=0;j<16;j++) q[j] += vv[c]*w[c*16+j];
    }
    float4* qo = (float4*)(outq + (size_t)n*16);
#pragma unroll
    for (int j=0;j<4;j++) qo[j] = make_float4(q[4*j],q[4*j+1],q[4*j+2],q[4*j+3]);
}

extern "C" void kernel_launch(void* const* d_in, const int* in_sizes, int n_in,
                              void* d_out, int out_size) {
    const float* inputs = (const float*)d_in[0];
    const void*  edge   = d_in[2];
    const float* W1     = (const float*)d_in[3];
    const float* b1     = (const float*)d_in[4];
    const float* p      = (const float*)d_in[5];
    const float* W_ih   = (const float*)d_in[6];
    const float* W_hh   = (const float*)d_in[7];
    const float* b_ih   = (const float*)d_in[8];
    const float* b_hh   = (const float*)d_in[9];
    const float* iw     = (const float*)d_in[10];
    const float* W2     = (const float*)d_in[11];
    const float* b2     = (const float*)d_in[12];

    int N = in_sizes[0] / 64;
    int E = in_sizes[2] / 2;
    float* outq = (float*)d_out;
    float* outh = (float*)d_out + (size_t)N*16;

    int nb128 = (N + 127) / 128;

    detect_kernel<<<1,32>>>(edge, N);
    pnorm_kernel<<<1,128>>>(p);
    gemm_kernel<<<nb128,256>>>(inputs, W1, b1, N, 64, 0);
    score_kernel<<<(N*32+255)/256,256>>>(p, N);
    chunk_sort_kernel<<<nb128,128>>>(N);
    int M = nb128, srcA = 1;
    while (M > 1){
        int nb = (M+1)/2;
        topk_merge<<<nb,128>>>(M, srcA);
        M = nb; srcA ^= 1;
    }
    build_xtilde<<<128,128>>>(srcA);
    gru_gemm<<<dim3(384,2),128>>>(W_ih, W_hh, b_ih, b_hh, iw);
    gates_kernel<<<64,256>>>(iw);
    deg_init<<<(N+255)/256,256>>>(N);
    deg_count<<<(E+255)/256,256>>>(edge, E);
    dinv_kernel<<<(N+255)/256,256>>>(N);
    ax_init<<<(N*128+255)/256,256>>>(N);
    scatter_kernel<<<(E*32+255)/256,256>>>(edge, E);
    gemm_kernel<<<nb128,256>>>(inputs, W1, nullptr, N, 128, 1);
    final_kernel<<<(N+255)/256,256>>>(W2, b2, outq, outh, N);
}

// round 5
// speedup vs baseline: 1.5905x; 1.5905x over previous
#include <cuda_runtime.h>
#include <cstdint>

typedef unsigned long long ull;
#define MAXN 100096
#define MAXE 1700000

__device__ float g_AX[MAXN*128];
__device__ ull   g_keys [MAXN];
__device__ ull   g_candA[MAXN];
__device__ ull   g_candB[MAXN];
__device__ float g_xt [128*128];
__device__ float g_gi [128*384];
__device__ float g_gh [128*384];
__device__ float g_wev[128*128];
__device__ float g_dinv[MAXN];
__device__ int   g_cnt [MAXN];
__device__ int   g_off [MAXN+1];
__device__ int   g_cur [MAXN];
__device__ int   g_rows[MAXE];
__device__ int   g_bsum[256];
__device__ int   g_boff[256];
__device__ float g_pinv;
__device__ int   g_e64;

__global__ void pnorm_kernel(const float* __restrict__ p){
    __shared__ float s[128];
    int i = threadIdx.x;
    float v = p[i];
    s[i] = v*v; __syncthreads();
    for (int o=64;o>0;o>>=1){ if (i<o) s[i]+=s[i+o]; __syncthreads(); }
    if (i==0) g_pinv = rsqrtf(s[0]);
}

__global__ void detect_kernel(const void* __restrict__ edge, int N){
    if (threadIdx.x==0){
        const long long* e = (const long long*)edge;
        int ok = 1;
        for (int i=0;i<8;i++){ long long v=e[i]; if (v<0 || v>=(long long)N) ok=0; }
        g_e64 = ok;
    }
}

__device__ __forceinline__ int edge_at(const void* edge, size_t idx){
    return g_e64 ? ((const int*)edge)[2*idx] : ((const int*)edge)[idx];
}

// ---------------- CSR build ------------------------------------------------
__global__ void zero_cnt(int N){
    int i = blockIdx.x*blockDim.x + threadIdx.x;
    if (i<N) g_cnt[i]=0;
}
__global__ void cnt_count(const void* __restrict__ edge, int E){
    int e = blockIdx.x*blockDim.x + threadIdx.x;
    if (e<E) atomicAdd(&g_cnt[edge_at(edge,(size_t)E+e)],1);
}
__global__ void dinv_kernel(int N){
    int i = blockIdx.x*blockDim.x + threadIdx.x;
    if (i<N) g_dinv[i] = rsqrtf((float)(g_cnt[i]+1));
}
__global__ void scan1(int N){
    __shared__ int s[512];
    int t = threadIdx.x;
    int i = blockIdx.x*512 + t;
    int v = (i<N) ? g_cnt[i] : 0;
    s[t]=v; __syncthreads();
    for (int o=1;o<512;o<<=1){
        int tmp = (t>=o)? s[t-o] : 0; __syncthreads();
        s[t]+=tmp; __syncthreads();
    }
    if (i<N) g_off[i] = s[t]-v;
    if (t==511) g_bsum[blockIdx.x] = s[511];
}
__global__ void scan2(int nb){
    __shared__ int s[256];
    int t=threadIdx.x;
    int v = (t<nb)? g_bsum[t] : 0;
    s[t]=v; __syncthreads();
    for (int o=1;o<256;o<<=1){
        int tmp=(t>=o)?s[t-o]:0; __syncthreads();
        s[t]+=tmp; __syncthreads();
    }
    g_boff[t] = s[t]-v;
}
__global__ void scan3(int N, int E){
    int i = blockIdx.x*blockDim.x + threadIdx.x;
    if (i<N){
        int v = g_off[i] + g_boff[i>>9];
        g_off[i]=v; g_cur[i]=v;
    }
    if (i==0) g_off[N]=E;
}
__global__ void fill_kernel(const void* __restrict__ edge, int E){
    int e = blockIdx.x*blockDim.x + threadIdx.x;
    if (e>=E) return;
    int r = edge_at(edge,(size_t)e);
    int c = edge_at(edge,(size_t)E+e);
    int pos = atomicAdd(&g_cur[c],1);
    g_rows[pos] = r;
}

// ------------- GEMM C[N,128]=A[N,K]@B[K,128], writes into out h-buffer -----
// mode 0: inputs@W1+b1, relu, col offset 128, fused top-k score/keys
// mode 1: g_AX@g_wev (B selected IN DEVICE CODE), col offset 0
__global__ __launch_bounds__(256) void gemm_kernel(const float* __restrict__ Aext,
                                                   const float* __restrict__ Bext,
                                                   const float* __restrict__ bias,
                                                   const float* __restrict__ p,
                                                   float* __restrict__ outh,
                                                   int N, int K, int mode){
    const float* A = (mode==0) ? Aext : g_AX;
    const float* B = (mode==0) ? Bext : g_wev;   // device-side symbol selection (the R4 bug fix)
    __shared__ float sA[128*33];
    __shared__ float sW[32*132];
    int tid = threadIdx.x;
    int tx = tid & 15, ty = tid >> 4;
    int rowBase = blockIdx.x << 7;
    float acc[8][8];
#pragma unroll
    for (int i=0;i<8;i++)
#pragma unroll
        for (int j=0;j<8;j++) acc[i][j]=0.f;

    for (int kk=0; kk<K; kk+=32){
#pragma unroll
        for (int r=0;r<4;r++){
            int f = tid + (r<<8);
            int row = f>>3, kc4 = f&7;
            float4 v = make_float4(0.f,0.f,0.f,0.f);
            int gr = rowBase + row;
            if (gr < N) v = *(const float4*)(A + (size_t)gr*K + kk + (kc4<<2));
            int o = row*33 + (kc4<<2);
            sA[o]=v.x; sA[o+1]=v.y; sA[o+2]=v.z; sA[o+3]=v.w;
        }
#pragma unroll
        for (int r=0;r<4;r++){
            int f = tid + (r<<8);
            int kr = f>>5, c4 = f&31;
            *(float4*)&sW[kr*132 + (c4<<2)] = *(const float4*)(B + (size_t)(kk+kr)*128 + (c4<<2));
        }
        __syncthreads();
#pragma unroll 8
        for (int kc=0;kc<32;kc++){
            float a[8];
#pragma unroll
            for (int i=0;i<8;i++) a[i] = sA[(ty + (i<<4))*33 + kc];
            float4 w0 = *(const float4*)&sW[kc*132 + (tx<<3)];
            float4 w1 = *(const float4*)&sW[kc*132 + (tx<<3) + 4];
#pragma unroll
            for (int i=0;i<8;i++){
                acc[i][0]+=a[i]*w0.x; acc[i][1]+=a[i]*w0.y; acc[i][2]+=a[i]*w0.z; acc[i][3]+=a[i]*w0.w;
                acc[i][4]+=a[i]*w1.x; acc[i][5]+=a[i]*w1.y; acc[i][6]+=a[i]*w1.z; acc[i][7]+=a[i]*w1.w;
            }
        }
        __syncthreads();
    }
    float bj[8], pv[8];
#pragma unroll
    for (int j=0;j<8;j++){
        bj[j] = bias ? bias[(tx<<3)+j] : 0.f;
        pv[j] = (mode==0) ? p[(tx<<3)+j] : 0.f;
    }
    int colOff = (mode==0) ? 128 : 0;
#pragma unroll
    for (int i=0;i<8;i++){
        int gr = rowBase + ty + (i<<4);
        bool ok = (gr < N);
        float o[8];
#pragma unroll
        for (int j=0;j<8;j++){
            float t = acc[i][j] + bj[j];
            o[j] = (mode==0) ? fmaxf(t,0.f) : t;
        }
        if (ok){
            float* cp = outh + (size_t)gr*256 + colOff + (tx<<3);
            *(float4*)cp       = make_float4(o[0],o[1],o[2],o[3]);
            *(float4*)(cp + 4) = make_float4(o[4],o[5],o[6],o[7]);
        }
        if (mode==0){
            float dot = 0.f;
#pragma unroll
            for (int j=0;j<8;j++) dot += o[j]*pv[j];
#pragma unroll
            for (int m=1;m<16;m<<=1) dot += __shfl_xor_sync(0xffffffffu, dot, m);
            if (tx==0 && ok){
                float sc = tanhf(dot * g_pinv);
                unsigned u = __float_as_uint(sc);
                unsigned ord = (u & 0x80000000u) ? ~u : (u | 0x80000000u);
                g_keys[gr] = ((ull)ord << 32) | (ull)(0xFFFFFFFFu - (unsigned)gr);
            }
        }
    }
}

// ---------------- top-k ----------------------------------------------------
__global__ void chunk_sort_kernel(int N){
    __shared__ ull s[128];
    int i = threadIdx.x;
    int g = (blockIdx.x<<7) + i;
    s[i] = (g < N) ? g_keys[g] : 0ULL;
    __syncthreads();
    for (int k=2;k<=128;k<<=1){
        for (int j=k>>1;j>0;j>>=1){
            int pi = i ^ j;
            ull x = s[i], y = s[pi];
            __syncthreads();
            bool desc = ((i & k) == 0);
            ull keep;
            if (i < pi) keep = desc ? (x>y?x:y) : (x<y?x:y);
            else        keep = desc ? (x<y?x:y) : (x>y?x:y);
            s[i] = keep;
            __syncthreads();
        }
    }
    g_candA[(blockIdx.x<<7)+i] = s[i];
}

__global__ void topk_merge4(int M, int srcIsA){
    const ull* src = srcIsA ? g_candA : g_candB;
    ull*       dst = srcIsA ? g_candB : g_candA;
    __shared__ ull s[256];
    int b = blockIdx.x, t = threadIdx.x;
    int half = t>>7, i = t&127;
    int l0 = 4*b + 2*half, l1 = l0+1;
    ull a  = (l0<M) ? src[(l0<<7)+i]        : 0ULL;
    ull bb = (l1<M) ? src[(l1<<7)+(127-i)]  : 0ULL;
    s[t] = (a > bb) ? a : bb;
    __syncthreads();
    for (int j=64;j>0;j>>=1){
        int pi = t ^ j;
        ull x = s[t], y = s[pi];
        __syncthreads();
        s[t] = (t < pi) ? (x>y?x:y) : (x<y?x:y);
        __syncthreads();
    }
    ull fa = s[t];
    ull fb = s[255 - t];
    __syncthreads();
    if (t < 128) s[t] = (fa > fb) ? fa : fb;
    __syncthreads();
    for (int j=64;j>0;j>>=1){
        int pi = t ^ j;
        ull x = s[t], y = s[pi];
        __syncthreads();
        if (t < 128) s[t] = (t < pi) ? (x>y?x:y) : (x<y?x:y);
        __syncthreads();
    }
    if (t < 128) dst[(b<<7)+t] = s[t];
}

__global__ void build_xtilde(int finalIsA, const float* __restrict__ outh){
    const ull* top = finalIsA ? g_candA : g_candB;
    int k = blockIdx.x;
    ull key = top[k];
    unsigned idx = 0xFFFFFFFFu - (unsigned)(key & 0xFFFFFFFFull);
    unsigned ord = (unsigned)(key >> 32);
    unsigned u = (ord & 0x80000000u) ? (ord & 0x7FFFFFFFu) : ~ord;
    float val = __uint_as_float(u);
    g_xt[(k<<7) + threadIdx.x] = outh[(size_t)idx*256 + 128 + threadIdx.x] * val;
}

// ---------------- GRU ------------------------------------------------------
__global__ void gru_gemm(const float* __restrict__ W_ih, const float* __restrict__ W_hh,
                         const float* __restrict__ b_ih, const float* __restrict__ b_hh,
                         const float* __restrict__ h0){
    int j = blockIdx.x;
    int isH = blockIdx.y;
    __shared__ float4 w[32];
    const float* W = isH ? W_hh : W_ih;
    if (threadIdx.x < 32) w[threadIdx.x] = ((const float4*)(W + (j<<7)))[threadIdx.x];
    __syncthreads();
    int k = threadIdx.x;
    const float4* src = (const float4*)((isH ? h0 : g_xt) + (k<<7));
    float s = 0.f;
#pragma unroll
    for (int h=0;h<32;h++){
        float4 aa = src[h], ww = w[h];
        s += aa.x*ww.x + aa.y*ww.y + aa.z*ww.z + aa.w*ww.w;
    }
    s += isH ? b_hh[j] : b_ih[j];
    (isH ? g_gh : g_gi)[k*384 + j] = s;
}

__global__ void gates_kernel(const float* __restrict__ h0){
    int t = blockIdx.x*blockDim.x + threadIdx.x;
    int k = t >> 7, c = t & 127;
    float ir = g_gi[k*384 + c],       hr = g_gh[k*384 + c];
    float iz = g_gi[k*384 + 128 + c], hz = g_gh[k*384 + 128 + c];
    float in_= g_gi[k*384 + 256 + c], hn = g_gh[k*384 + 256 + c];
    float r = 1.f/(1.f + expf(-(ir+hr)));
    float z = 1.f/(1.f + expf(-(iz+hz)));
    float nn = tanhf(in_ + r*hn);
    g_wev[(k<<7)+c] = (1.f - z)*nn + z*h0[(k<<7)+c];
}

// ---------------- CSR gather: AX[c] = dinv[c]*(dinv[c]X[c]+sum dinv[r]X[r]) -
__global__ __launch_bounds__(256) void gather_kernel(const float* __restrict__ outh, int N){
    int gt = blockIdx.x*blockDim.x + threadIdx.x;
    int c = gt>>5, lane = gt&31;
    if (c >= N) return;
    int beg = g_off[c], end = g_off[c+1];
    float dc = g_dinv[c];
    float4 a0 = *((const float4*)(outh + (size_t)c*256 + 128) + lane);
    a0.x*=dc; a0.y*=dc; a0.z*=dc; a0.w*=dc;
    float4 a1 = make_float4(0.f,0.f,0.f,0.f);
    int k = beg;
    for (; k+2 <= end; k += 2){
        int r0 = g_rows[k], r1 = g_rows[k+1];
        float d0 = g_dinv[r0], d1 = g_dinv[r1];
        float4 v0 = *((const float4*)(outh + (size_t)r0*256 + 128) + lane);
        float4 v1 = *((const float4*)(outh + (size_t)r1*256 + 128) + lane);
        a0.x+=d0*v0.x; a0.y+=d0*v0.y; a0.z+=d0*v0.z; a0.w+=d0*v0.w;
        a1.x+=d1*v1.x; a1.y+=d1*v1.y; a1.z+=d1*v1.z; a1.w+=d1*v1.w;
    }
    if (k < end){
        int r0 = g_rows[k];
        float d0 = g_dinv[r0];
        float4 v0 = *((const float4*)(outh + (size_t)r0*256 + 128) + lane);
        a0.x+=d0*v0.x; a0.y+=d0*v0.y; a0.z+=d0*v0.z; a0.w+=d0*v0.w;
    }
    float4 r;
    r.x = dc*(a0.x+a1.x); r.y = dc*(a0.y+a1.y);
    r.z = dc*(a0.z+a1.z); r.w = dc*(a0.w+a1.w);
    *((float4*)(g_AX + ((size_t)c<<7)) + lane) = r;
}

// ---------------- q = h@W2 + b2 --------------------------------------------
__global__ __launch_bounds__(256) void final_kernel(const float* __restrict__ W2,
                                                    const float* __restrict__ b2,
                                                    float* __restrict__ outq,
                                                    const float* __restrict__ outh, int N){
    __shared__ float sW2[4096];
    for (int i=threadIdx.x;i<4096;i+=256) sW2[i]=W2[i];
    __syncthreads();
    int n = blockIdx.x*256 + threadIdx.x;
    if (n >= N) return;
    const float4* h4 = (const float4*)(outh + (size_t)n*256);
    float q[16];
#pragma unroll
    for (int j=0;j<16;j++) q[j]=b2[j];
#pragma unroll 4
    for (int j4=0;j4<64;j4++){
        float4 v = h4[j4];
        const float* w = &sW2[(j4<<2)*16];
        float vv[4] = {v.x,v.y,v.z,v.w};
#pragma unroll
        for (int c=0;c<4;c++)
#pragma unroll
            for (int j=0;j<16;j++) q[j] += vv[c]*w[c*16+j];
    }
    float4* qo = (float4*)(outq + (size_t)n*16);
#pragma unroll
    for (int j=0;j<4;j++) qo[j] = make_float4(q[4*j],q[4*j+1],q[4*j+2],q[4*j+3]);
}

extern "C" void kernel_launch(void* const* d_in, const int* in_sizes, int n_in,
                              void* d_out, int out_size) {
    const float* inputs = (const float*)d_in[0];
    const void*  edge   = d_in[2];
    const float* W1     = (const float*)d_in[3];
    const float* b1     = (const float*)d_in[4];
    const float* p      = (const float*)d_in[5];
    const float* W_ih   = (const float*)d_in[6];
    const float* W_hh   = (const float*)d_in[7];
    const float* b_ih   = (const float*)d_in[8];
    const float* b_hh   = (const float*)d_in[9];
    const float* iw     = (const float*)d_in[10];
    const float* W2     = (const float*)d_in[11];
    const float* b2     = (const float*)d_in[12];

    int N = in_sizes[0] / 64;
    int E = in_sizes[2] / 2;
    float* outq = (float*)d_out;
    float* outh = (float*)d_out + (size_t)N*16;

    int nb128 = (N + 127) / 128;
    int nbScan = (N + 511) / 512;

    detect_kernel<<<1,32>>>(edge, N);
    pnorm_kernel<<<1,128>>>(p);
    // CSR build + norms
    zero_cnt<<<(N+255)/256,256>>>(N);
    cnt_count<<<(E+255)/256,256>>>(edge, E);
    dinv_kernel<<<(N+255)/256,256>>>(N);
    scan1<<<nbScan,512>>>(N);
    scan2<<<1,256>>>(nbScan);
    scan3<<<(N+255)/256,256>>>(N, E);
    fill_kernel<<<(E+255)/256,256>>>(edge, E);
    // x = relu(inputs@W1+b1) -> outh[:,128:], fused scores
    gemm_kernel<<<nb128,256>>>(inputs, W1, b1, p, outh, N, 64, 0);
    // top-128
    chunk_sort_kernel<<<nb128,128>>>(N);
    int M = nb128, srcA = 1;
    while (M > 1){
        int nb = (M+3)/4;
        topk_merge4<<<nb,256>>>(M, srcA);
        M = nb; srcA ^= 1;
    }
    build_xtilde<<<128,128>>>(srcA, outh);
    // GRU weight evolution
    gru_gemm<<<dim3(384,2),128>>>(W_ih, W_hh, b_ih, b_hh, iw);
    gates_kernel<<<64,256>>>(iw);
    // normalized aggregation via CSR gather
    gather_kernel<<<(N*32+255)/256,256>>>(outh, N);
    // h_gcn = AX @ W_evolved -> outh[:,0:128]
    gemm_kernel<<<nb128,256>>>(nullptr, nullptr, nullptr, nullptr, outh, N, 128, 1);
    // q = h@W2+b2
    final_kernel<<<(N+255)/256,256>>>(W2, b2, outq, outh, N);
}